// round 1
// baseline (speedup 1.0000x reference)
#include <cuda_runtime.h>
#include <cuda_bf16.h>
#include <cstdint>

// ---------------- scratch (static __device__, no allocation) ----------------
__device__ float g_conv[8192 * 256];    // conv_all  [B*S, 256]
__device__ float g_x[8192 * 256];       // layer input/output [B*S, 256]
__device__ float g_gates[8192 * 768];   // xg for one layer, both dirs [B*S, 768]

// ---------------- constants ----------------
#define Bsz 128
#define Ssz 64
#define Psz 32
#define Dsz 256
#define Hsz 128

// =====================================================================
// Kernel 1: fused conv scalar + weighted event sum.
//   s_p = dot(inputs[b,s,p,:], conv_w) + conv_b
//   conv_all[b,s,k] = sum_p s_p * inputs[b,s,p,k]
// one block per (b,s); HBM streaming bound.
// =====================================================================
__global__ __launch_bounds__(256)
void conv_kernel(const float* __restrict__ in, const float* __restrict__ conv_w,
                 const float* __restrict__ conv_b, float* __restrict__ out)
{
    __shared__ __align__(16) float tile[Psz * Dsz];   // 32 KB
    __shared__ float cw[Dsz];
    __shared__ float sp[Psz];

    const int tid = threadIdx.x;
    const float* src = in + (size_t)blockIdx.x * (Psz * Dsz);

    cw[tid] = conv_w[tid];
    // vectorized tile load: 8192 floats = 2048 float4
    const float4* src4 = (const float4*)src;
    float4* tile4 = (float4*)tile;
#pragma unroll
    for (int i = 0; i < 8; i++)
        tile4[tid + i * 256] = src4[tid + i * 256];
    __syncthreads();

    const int warp = tid >> 5, lane = tid & 31;
#pragma unroll
    for (int r = 0; r < 4; r++) {
        int p = warp * 4 + r;
        float acc = 0.f;
#pragma unroll
        for (int j = 0; j < 8; j++)
            acc += tile[p * Dsz + lane + j * 32] * cw[lane + j * 32];
#pragma unroll
        for (int o = 16; o; o >>= 1)
            acc += __shfl_xor_sync(0xffffffffu, acc, o);
        if (lane == 0) sp[p] = acc + conv_b[0];
    }
    __syncthreads();

    float acc = 0.f;
#pragma unroll
    for (int p = 0; p < Psz; p++)
        acc += sp[p] * tile[p * Dsz + tid];
    out[(size_t)blockIdx.x * Dsz + tid] = acc;
}

// =====================================================================
// Kernel 2: generic SGEMM  C[m,n] = sum_k A[m,k]*B[n,k] (+bias[n]) (clip)
// A: [M,K] row-major, B: [N,K] row-major. BM=128 BN=64 BK=16, 256 thr, 8x4.
// All our shapes divide the tiles evenly.
// =====================================================================
#define BM 128
#define BN 64
#define BK 16

template<bool CLIP, bool BIAS>
__global__ __launch_bounds__(256)
void sgemm_nt(const float* __restrict__ A, const float* __restrict__ B,
              const float* __restrict__ bias, float* __restrict__ C,
              int M, int N, int K)
{
    __shared__ float As[BK][BM + 4];
    __shared__ float Bs[BK][BN + 4];

    const int tid = threadIdx.x;
    const int bm = blockIdx.y * BM;
    const int bn = blockIdx.x * BN;

    const int lrow = tid >> 2;           // 0..63
    const int lk   = (tid & 3) * 4;      // 0,4,8,12

    const int tx = tid & 15;             // n-tile
    const int ty = tid >> 4;             // m-tile

    float acc[8][4];
#pragma unroll
    for (int i = 0; i < 8; i++)
#pragma unroll
        for (int j = 0; j < 4; j++) acc[i][j] = 0.f;

    for (int kt = 0; kt < K; kt += BK) {
        float4 a0 = *(const float4*)&A[(size_t)(bm + lrow) * K + kt + lk];
        float4 a1 = *(const float4*)&A[(size_t)(bm + lrow + 64) * K + kt + lk];
        float4 b0 = *(const float4*)&B[(size_t)(bn + lrow) * K + kt + lk];
        __syncthreads();
        As[lk + 0][lrow] = a0.x; As[lk + 1][lrow] = a0.y;
        As[lk + 2][lrow] = a0.z; As[lk + 3][lrow] = a0.w;
        As[lk + 0][lrow + 64] = a1.x; As[lk + 1][lrow + 64] = a1.y;
        As[lk + 2][lrow + 64] = a1.z; As[lk + 3][lrow + 64] = a1.w;
        Bs[lk + 0][lrow] = b0.x; Bs[lk + 1][lrow] = b0.y;
        Bs[lk + 2][lrow] = b0.z; Bs[lk + 3][lrow] = b0.w;
        __syncthreads();
#pragma unroll
        for (int k = 0; k < BK; k++) {
            float4 av0 = *(const float4*)&As[k][ty * 8];
            float4 av1 = *(const float4*)&As[k][ty * 8 + 4];
            float4 bv  = *(const float4*)&Bs[k][tx * 4];
            float am[8] = {av0.x, av0.y, av0.z, av0.w, av1.x, av1.y, av1.z, av1.w};
            float bm_[4] = {bv.x, bv.y, bv.z, bv.w};
#pragma unroll
            for (int i = 0; i < 8; i++)
#pragma unroll
                for (int j = 0; j < 4; j++)
                    acc[i][j] += am[i] * bm_[j];
        }
    }

    float bset[4] = {0.f, 0.f, 0.f, 0.f};
    if (BIAS) {
#pragma unroll
        for (int j = 0; j < 4; j++) bset[j] = bias[bn + tx * 4 + j];
    }
#pragma unroll
    for (int i = 0; i < 8; i++) {
        float4 v;
        float* vp = (float*)&v;
#pragma unroll
        for (int j = 0; j < 4; j++) {
            float t = acc[i][j] + bset[j];
            if (CLIP) t = fminf(1.0f, fmaxf(-1.0f, t));
            vp[j] = t;
        }
        *(float4*)&C[(size_t)(bm + ty * 8 + i) * N + bn + tx * 4] = v;
    }
}

// =====================================================================
// Kernel 3: GRU scan for one layer, both directions.
// grid = 128 blocks: blockIdx = dir*64 + batch_pair. 384 threads.
// Thread g holds Whh row g (128 floats) in registers; processes 2 batch
// elements per step (FFMA-bound). h lives in SMEM; gate-combine by thr<256.
// gates: [B*S, 768] (cols dir*384+g, bih already added).
// out:   [B*S, 256] (cols dir*128+j).
// =====================================================================
__device__ __forceinline__ float sigmoidf_(float x) { return 1.0f / (1.0f + expf(-x)); }

__global__ __launch_bounds__(384, 1)
void gru_scan(const float* __restrict__ gates, const float* __restrict__ Whh,
              const float* __restrict__ bhh, float* __restrict__ out)
{
    const int dir = blockIdx.x >> 6;
    const int bpair = blockIdx.x & 63;
    const int b0 = bpair * 2;
    const int g = threadIdx.x;

    // register-resident weight row
    const float4* W4 = (const float4*)(Whh + (size_t)dir * 384 * 128 + (size_t)g * 128);
    float4 w[32];
#pragma unroll
    for (int i = 0; i < 32; i++) w[i] = W4[i];
    const float bias = bhh[dir * 384 + g];

    __shared__ __align__(16) float h0[Hsz];
    __shared__ __align__(16) float h1[Hsz];
    __shared__ float gh0[384];
    __shared__ float gh1[384];

    if (g < Hsz) { h0[g] = 0.f; h1[g] = 0.f; }
    __syncthreads();

    // gate-combine role for threads < 256
    const int j = g & 127;
    const int isb1 = (g >= 128 && g < 256) ? 1 : 0;
    const int bc = b0 + isb1;

    for (int t_ = 0; t_ < Ssz; t_++) {
        const int t = dir ? (Ssz - 1 - t_) : t_;

        // early-issue global loads of xg for the combine phase (hidden by matvec)
        float xr = 0.f, xz = 0.f, xn = 0.f;
        if (g < 256) {
            const float* gb = gates + ((size_t)(bc * Ssz + t)) * 768 + dir * 384;
            xr = gb[j];
            xz = gb[128 + j];
            xn = gb[256 + j];
        }

        // matvec: gh = Whh @ h + bhh, both batches
        const float4* hv0p = (const float4*)h0;
        const float4* hv1p = (const float4*)h1;
        float a0 = bias, a1 = bias;
#pragma unroll
        for (int i = 0; i < 32; i++) {
            float4 hv0 = hv0p[i];
            float4 hv1 = hv1p[i];
            a0 += w[i].x * hv0.x; a1 += w[i].x * hv1.x;
            a0 += w[i].y * hv0.y; a1 += w[i].y * hv1.y;
            a0 += w[i].z * hv0.z; a1 += w[i].z * hv1.z;
            a0 += w[i].w * hv0.w; a1 += w[i].w * hv1.w;
        }
        gh0[g] = a0;
        gh1[g] = a1;
        __syncthreads();

        if (g < 256) {
            float* h  = isb1 ? h1 : h0;
            float* gh = isb1 ? gh1 : gh0;
            float r = sigmoidf_(xr + gh[j]);
            float z = sigmoidf_(xz + gh[128 + j]);
            float n = tanhf(xn + r * gh[256 + j]);
            float hnew = (1.0f - z) * n + z * h[j];
            h[j] = hnew;
            out[((size_t)(bc * Ssz + t)) * 256 + dir * 128 + j] = hnew;
        }
        __syncthreads();
    }
}

// =====================================================================
// Kernel 4: epilogue. alpha == 1 exactly (softmax over singleton axis).
// context[b,h] = sum_s states[b,s,h]; out = softmax(context @ lin_w.T + lin_b)
// =====================================================================
__global__ __launch_bounds__(256)
void epilogue_kernel(const float* __restrict__ states, const float* __restrict__ lin_w,
                     const float* __restrict__ lin_b, float* __restrict__ out_out,
                     float* __restrict__ out_ctx, float* __restrict__ out_alpha)
{
    __shared__ float ctx[256];
    __shared__ float logits[2];
    const int b = blockIdx.x;
    const int tid = threadIdx.x;

    const float* sb = states + (size_t)b * Ssz * 256;
    float acc = 0.f;
#pragma unroll
    for (int s = 0; s < Ssz; s++)
        acc += sb[s * 256 + tid];
    ctx[tid] = acc;
    out_ctx[(size_t)b * 256 + tid] = acc;
    if (tid < Ssz) out_alpha[(size_t)b * Ssz + tid] = 1.0f;
    __syncthreads();

    if (tid < 64) {
        const int o = tid >> 5, lane = tid & 31;
        float p = 0.f;
#pragma unroll
        for (int k = 0; k < 8; k++)
            p += ctx[lane + k * 32] * lin_w[o * 256 + lane + k * 32];
#pragma unroll
        for (int off = 16; off; off >>= 1)
            p += __shfl_xor_sync(0xffffffffu, p, off);
        if (lane == 0) logits[o] = p + lin_b[o];
    }
    __syncthreads();
    if (tid == 0) {
        float l0 = logits[0], l1 = logits[1];
        float m = fmaxf(l0, l1);
        float e0 = expf(l0 - m), e1 = expf(l1 - m);
        float inv = 1.0f / (e0 + e1);
        out_out[b * 2 + 0] = e0 * inv;
        out_out[b * 2 + 1] = e1 * inv;
    }
}

// =====================================================================
// launcher
// =====================================================================
extern "C" void kernel_launch(void* const* d_in, const int* in_sizes, int n_in,
                              void* d_out, int out_size)
{
    const float* inputs  = (const float*)d_in[0];   // [128,64,32,256]
    const float* conv_w  = (const float*)d_in[1];   // [256]
    const float* conv_b  = (const float*)d_in[2];   // [1]
    const float* embed_w = (const float*)d_in[3];   // [256,256]
    const float* Wih     = (const float*)d_in[4];   // [2,2,384,256]
    const float* Whh     = (const float*)d_in[5];   // [2,2,384,128]
    const float* bih     = (const float*)d_in[6];   // [2,2,384]
    const float* bhh     = (const float*)d_in[7];   // [2,2,384]
    // d_in[8] = att_w1: mathematically unused (A==1 -> softmax == 1)
    const float* lin_w   = (const float*)d_in[9];   // [2,256]
    const float* lin_b   = (const float*)d_in[10];  // [2]

    float* out_base = (float*)d_out;
    // output tuple layout: out[128*2] | states[128*64*256] | context[128*256] | alpha[128*64]
    const int total_expected = 256 + 8192 * 256 + 128 * 256 + 128 * 64;
    float* out_out    = out_base;
    float* out_states = out_base + 256;
    float* out_ctx    = out_states + 8192 * 256;
    float* out_alpha  = out_ctx + 128 * 256;
    const bool full = (out_size >= total_expected);

    float *pconv, *px, *pgates;
    cudaGetSymbolAddress((void**)&pconv, g_conv);
    cudaGetSymbolAddress((void**)&px, g_x);
    cudaGetSymbolAddress((void**)&pgates, g_gates);

    // 1) fused conv + weighted sum -> g_conv [8192,256]
    conv_kernel<<<Bsz * Ssz, 256>>>(inputs, conv_w, conv_b, pconv);

    // 2) embed + hardtanh -> g_x [8192,256]
    sgemm_nt<true, false><<<dim3(256 / BN, 8192 / BM), 256>>>(
        pconv, embed_w, nullptr, px, 8192, 256, 256);

    // 3) two bidirectional GRU layers
    for (int l = 0; l < 2; l++) {
        const float* WihL = Wih + (size_t)l * 2 * 384 * 256;
        const float* bihL = bih + (size_t)l * 2 * 384;
        const float* WhhL = Whh + (size_t)l * 2 * 384 * 128;
        const float* bhhL = bhh + (size_t)l * 2 * 384;

        // input gates xg = x @ WihL^T + bihL -> g_gates [8192,768]
        sgemm_nt<false, true><<<dim3(768 / BN, 8192 / BM), 256>>>(
            px, WihL, bihL, pgates, 8192, 768, 256);

        float* dst = (l == 0) ? px : (full ? out_states : px);
        gru_scan<<<128, 384>>>(pgates, WhhL, bhhL, dst);
    }

    // 4) epilogue: context / alpha / output softmax
    const float* states_src = full ? out_states : px;
    if (full) {
        epilogue_kernel<<<Bsz, 256>>>(states_src, lin_w, lin_b,
                                      out_out, out_ctx, out_alpha);
    } else {
        // fallback: only the first output fits; reuse g_conv as ctx scratch
        epilogue_kernel<<<Bsz, 256>>>(states_src, lin_w, lin_b,
                                      out_out, pconv, pconv + 128 * 256);
    }
}